// round 13
// baseline (speedup 1.0000x reference)
#include <cuda_runtime.h>
#include <cuda_bf16.h>
#include <math.h>
#include <stdint.h>

#define BATCH 32
#define HH 56
#define WW 56
#define CC 192
#define NHEAD 6
#define HDIM 32
#define NTOK 49
#define HIDDEN 768
#define TOKENS (BATCH*HH*WW)   // 100352

// Scratch (device globals — no runtime allocation allowed)
__device__ float g_buf0[TOKENS*CC];             // shortcut (after cpe0)
__device__ float g_buf1[TOKENS*CC];             // y (after attn residual)
__device__ float g_buf2[TOKENS*CC];             // y2 (after cpe1)
__device__ __nv_bfloat16 g_xn  [TOKENS*CC];     // LN output (bf16)
__device__ __nv_bfloat16 g_attn[TOKENS*CC];     // attention output (bf16)
__device__ __nv_bfloat16 g_qkv [TOKENS*3*CC];   // qkv bf16 [tok][kqv][head][32]
__device__ __nv_bfloat16 g_wqkv[576*192];       // [N][K] bf16
__device__ float        g_bqkv[576];
__device__ __nv_bfloat16 g_wproj[192*192];
__device__ __nv_bfloat16 g_wfc1[768*192];
__device__ __nv_bfloat16 g_wfc2[192*768];

__device__ __forceinline__ float gelu_exact(float x) {
    return 0.5f * x * (1.f + erff(x * 0.7071067811865475f));
}
__device__ __forceinline__ void cp_async16(void* smem, const void* gmem) {
    unsigned s = (unsigned)__cvta_generic_to_shared(smem);
    asm volatile("cp.async.cg.shared.global [%0], [%1], 16;" :: "r"(s), "l"(gmem));
}
__device__ __forceinline__ void cp_commit() {
    asm volatile("cp.async.commit_group;");
}
template<int N> __device__ __forceinline__ void cp_wait() {
    asm volatile("cp.async.wait_group %0;" :: "n"(N));
}
__device__ __forceinline__ void ldsm_x4(uint32_t* r, uint32_t addr) {
    asm volatile("ldmatrix.sync.aligned.m8n8.x4.shared.b16 {%0,%1,%2,%3}, [%4];"
        : "=r"(r[0]), "=r"(r[1]), "=r"(r[2]), "=r"(r[3]) : "r"(addr));
}
__device__ __forceinline__ void ldsm_x2(uint32_t* r, uint32_t addr) {
    asm volatile("ldmatrix.sync.aligned.m8n8.x2.shared.b16 {%0,%1}, [%2];"
        : "=r"(r[0]), "=r"(r[1]) : "r"(addr));
}
__device__ __forceinline__ void mma_bf16(float* c, const uint32_t* a,
                                         uint32_t b0, uint32_t b1) {
    asm volatile(
        "mma.sync.aligned.m16n8k16.row.col.f32.bf16.bf16.f32 "
        "{%0,%1,%2,%3}, {%4,%5,%6,%7}, {%8,%9}, {%0,%1,%2,%3};"
        : "+f"(c[0]), "+f"(c[1]), "+f"(c[2]), "+f"(c[3])
        : "r"(a[0]), "r"(a[1]), "r"(a[2]), "r"(a[3]), "r"(b0), "r"(b1));
}

// ---------------------------------------------------------------------------
// One-shot weight prep (4 jobs merged): W[K][N] -> Wt[N][K], bf16.
// Job 0 also applies the faithful (d k h) qkv column permutation.
// ---------------------------------------------------------------------------
__global__ void prep_weights(
    const float* __restrict__ qkv_w, const float* __restrict__ qkv_b,
    const float* __restrict__ proj_w, const float* __restrict__ fc1_w,
    const float* __restrict__ fc2_w,
    __nv_bfloat16* __restrict__ wqkv, float* __restrict__ bqkv,
    __nv_bfloat16* __restrict__ wproj, __nv_bfloat16* __restrict__ wfc1,
    __nv_bfloat16* __restrict__ wfc2)
{
    int job = blockIdx.y;
    int idx = blockIdx.x*256 + threadIdx.x;
    if (job == 0) {
        if (idx >= 576*192) return;
        int n = idx / 192, k = idx % 192;
        int kk = n / 192;
        int rem = n % 192;
        int h = rem / 32, d = rem % 32;
        int src = d*18 + kk*6 + h;
        wqkv[idx] = __float2bfloat16(qkv_w[(size_t)k*576 + src]);
        if (k == 0) bqkv[n] = qkv_b[src];
    } else if (job == 1) {
        if (idx >= 192*192) return;
        int n = idx / 192, k = idx % 192;
        wproj[idx] = __float2bfloat16(proj_w[(size_t)k*192 + n]);
    } else if (job == 2) {
        if (idx >= 768*192) return;
        int n = idx / 192, k = idx % 192;
        wfc1[idx] = __float2bfloat16(fc1_w[(size_t)k*768 + n]);
    } else {
        if (idx >= 192*768) return;
        int n = idx / 768, k = idx % 768;
        wfc2[idx] = __float2bfloat16(fc2_w[(size_t)k*192 + n]);
    }
}

// ---------------------------------------------------------------------------
// Depthwise 3x3 conv (SAME) + residual
// ---------------------------------------------------------------------------
__global__ void cpe_kernel(const float* __restrict__ in,
                           const float* __restrict__ wgt,
                           const float* __restrict__ bias,
                           float* __restrict__ out)
{
    int h = blockIdx.x;
    int b = blockIdx.y;
    int c = threadIdx.x;
    float kw[9];
#pragma unroll
    for (int i = 0; i < 9; i++) kw[i] = wgt[c*9 + i];
    float bb = bias[c];
    const float* base  = in  + ((size_t)b*HH*WW)*CC + c;
    float*       obase = out + ((size_t)b*HH*WW)*CC + c;

    float colL[3], colM[3], colR[3];
#pragma unroll
    for (int dy = 0; dy < 3; dy++) {
        colL[dy] = 0.f;
        int hy = h + dy - 1;
        colM[dy] = (hy >= 0 && hy < HH) ? base[(size_t)(hy*WW)*CC] : 0.f;
    }
    for (int x = 0; x < WW; x++) {
#pragma unroll
        for (int dy = 0; dy < 3; dy++) {
            int hy = h + dy - 1;
            colR[dy] = (x+1 < WW && hy >= 0 && hy < HH)
                       ? base[(size_t)(hy*WW + x + 1)*CC] : 0.f;
        }
        float acc = bb;
#pragma unroll
        for (int dy = 0; dy < 3; dy++) {
            acc = fmaf(kw[dy*3+0], colL[dy], acc);
            acc = fmaf(kw[dy*3+1], colM[dy], acc);
            acc = fmaf(kw[dy*3+2], colR[dy], acc);
        }
        obase[(size_t)(h*WW + x)*CC] = colM[1] + acc;
#pragma unroll
        for (int dy = 0; dy < 3; dy++) { colL[dy] = colM[dy]; colM[dy] = colR[dy]; }
    }
}

// ---------------------------------------------------------------------------
// Per-token LayerNorm -> bf16 output (feeds GEMMs only)
// ---------------------------------------------------------------------------
__global__ void ln_kernel(const float* __restrict__ in,
                          const float* __restrict__ g, const float* __restrict__ b,
                          __nv_bfloat16* __restrict__ out)
{
    int tok  = blockIdx.x*8 + (threadIdx.x >> 5);
    int lane = threadIdx.x & 31;
    const float* p = in + (size_t)tok*CC;
    __nv_bfloat16* o = out + (size_t)tok*CC;
    float vals[6]; float s = 0.f;
#pragma unroll
    for (int u = 0; u < 6; u++) { vals[u] = p[lane + u*32]; s += vals[u]; }
#pragma unroll
    for (int off = 16; off; off >>= 1) s += __shfl_xor_sync(0xffffffffu, s, off);
    float m = s * (1.f/192.f);
    float vv = 0.f;
#pragma unroll
    for (int u = 0; u < 6; u++) { float d = vals[u]-m; vv += d*d; }
#pragma unroll
    for (int off = 16; off; off >>= 1) vv += __shfl_xor_sync(0xffffffffu, vv, off);
    float rs = rsqrtf(vv*(1.f/192.f) + 1e-5f);
#pragma unroll
    for (int u = 0; u < 6; u++) {
        int c = lane + u*32;
        o[c] = __float2bfloat16((vals[u]-m)*rs*g[c] + b[c]);
    }
}

// ---------------------------------------------------------------------------
// bf16 mma.sync GEMM (round-9 proven config): 128x192 block, 256 threads
// (8 warps 2x4), warp tile 64x48. MODE: 2 = fp32 out + residual; 3 = bf16 out.
// ---------------------------------------------------------------------------
#define ASTG 10240
#define BSTG 15360
#define GEMM_SMEM_BYTES (3*(ASTG+BSTG))   // 76800

__device__ __forceinline__ void stage_bf16(
    char* sA, char* sB, const __nv_bfloat16* A, const __nv_bfloat16* Wt,
    int row0, int col0, int k0, int KTOT, int tid)
{
#pragma unroll
    for (int i = 0; i < 2; i++) {
        int idx = tid + i*256;
        int r = idx >> 2, q = idx & 3;
        cp_async16(sA + r*80 + q*16, A + (size_t)(row0 + r)*KTOT + k0 + q*8);
    }
#pragma unroll
    for (int i = 0; i < 3; i++) {
        int idx = tid + i*256;
        int n = idx >> 2, q = idx & 3;
        cp_async16(sB + n*80 + q*16, Wt + (size_t)(col0 + n)*KTOT + k0 + q*8);
    }
}

template<int KTOT, int MODE>
__global__ __launch_bounds__(256) void gemm_bf16(
    const __nv_bfloat16* __restrict__ A, const __nv_bfloat16* __restrict__ Wt,
    const float* __restrict__ bias, const float* __restrict__ res,
    void* __restrict__ outv, int N)
{
    extern __shared__ char smc[];
    const int NC = KTOT/32;
    int tid = threadIdx.x;
    int wid = tid >> 5, lane = tid & 31;
    int wm = wid >> 2, wn = wid & 3;
    int gid = lane >> 2, tig = lane & 3;
    int col0 = blockIdx.x * 192;
    int row0 = blockIdx.y * 128;

    float acc[4][6][4];
#pragma unroll
    for (int mi = 0; mi < 4; mi++)
#pragma unroll
        for (int ni = 0; ni < 6; ni++)
#pragma unroll
            for (int j = 0; j < 4; j++) acc[mi][ni][j] = 0.f;

#pragma unroll
    for (int c = 0; c < 3; c++) {
        stage_bf16(smc + c*ASTG, smc + 3*ASTG + c*BSTG, A, Wt,
                   row0, col0, c*32, KTOT, tid);
        cp_commit();
    }

    uint32_t sbase = (uint32_t)__cvta_generic_to_shared(smc);
    uint32_t aOff = (uint32_t)((wm*64 + (lane & 7) + ((lane >> 3) & 1)*8)*80
                               + ((lane >> 4) & 1)*16);
    int l2 = lane & 15;
    uint32_t bOff = (uint32_t)(3*ASTG + (wn*48 + (l2 & 7))*80 + ((l2 >> 3) & 1)*16);

    for (int c = 0; c < NC; c++) {
        if (c + 3 <= NC) cp_wait<2>();
        else if (c + 2 == NC) cp_wait<1>();
        else cp_wait<0>();
        __syncthreads();
        int st = c % 3;
        uint32_t aB = sbase + st*ASTG + aOff;
        uint32_t bB = sbase + st*BSTG + bOff;
#pragma unroll
        for (int ks = 0; ks < 2; ks++) {
            uint32_t av[4][4], bv[6][2];
#pragma unroll
            for (int mi = 0; mi < 4; mi++)
                ldsm_x4(av[mi], aB + mi*16*80 + ks*32);
#pragma unroll
            for (int ni = 0; ni < 6; ni++)
                ldsm_x2(bv[ni], bB + ni*8*80 + ks*32);
#pragma unroll
            for (int ni = 0; ni < 6; ni++)
#pragma unroll
                for (int mi = 0; mi < 4; mi++)
                    mma_bf16(acc[mi][ni], av[mi], bv[ni][0], bv[ni][1]);
        }
        __syncthreads();
        if (c + 3 < NC) {
            stage_bf16(smc + st*ASTG, smc + 3*ASTG + st*BSTG, A, Wt,
                       row0, col0, (c + 3)*32, KTOT, tid);
            cp_commit();
        }
    }

#pragma unroll
    for (int mi = 0; mi < 4; mi++) {
        int r0 = row0 + wm*64 + mi*16 + gid;
#pragma unroll
        for (int ni = 0; ni < 6; ni++) {
            int col = col0 + wn*48 + ni*8 + 2*tig;
            float2 bb = *(const float2*)&bias[col];
            float v0x = acc[mi][ni][0] + bb.x, v0y = acc[mi][ni][1] + bb.y;
            float v1x = acc[mi][ni][2] + bb.x, v1y = acc[mi][ni][3] + bb.y;
            size_t o0 = (size_t)r0*N + col;
            size_t o1 = (size_t)(r0 + 8)*N + col;
            if (MODE == 3) {
                __nv_bfloat16* out = (__nv_bfloat16*)outv;
                __nv_bfloat162 p0 = __floats2bfloat162_rn(v0x, v0y);
                __nv_bfloat162 p1 = __floats2bfloat162_rn(v1x, v1y);
                *(__nv_bfloat162*)&out[o0] = p0;
                *(__nv_bfloat162*)&out[o1] = p1;
            } else {
                float* out = (float*)outv;
                float2 r0v = *(const float2*)&res[o0];
                float2 r1v = *(const float2*)&res[o1];
                v0x += r0v.x; v0y += r0v.y;
                v1x += r1v.x; v1y += r1v.y;
                *(float2*)&out[o0] = make_float2(v0x, v0y);
                *(float2*)&out[o1] = make_float2(v1x, v1y);
            }
        }
    }
}

// ---------------------------------------------------------------------------
// Fused MLP (round-9 proven 256-thread config)
// ---------------------------------------------------------------------------
#define MSX  0
#define MSB1 51200
#define MSH  (51200+51200)
#define MSB2 (51200+51200+18432)
#define MLP_SMEM 176128

__device__ __forceinline__ void mlp_stage_b(
    char* smc, const __nv_bfloat16* wfc1, const __nv_bfloat16* wfc2,
    int t, int tid)
{
    char* b1 = smc + MSB1 + (t & 1)*25600;
    char* b2 = smc + MSB2 + (t & 1)*27648;
#pragma unroll
    for (int i = 0; i < 6; i++) {
        int idx = tid + i*256;
        int n = idx / 24, q = idx % 24;
        cp_async16(b1 + n*400 + q*16, wfc1 + (size_t)(t*64 + n)*192 + q*8);
    }
#pragma unroll
    for (int i = 0; i < 6; i++) {
        int idx = tid + i*256;
        int n = idx >> 3, q = idx & 7;
        cp_async16(b2 + n*144 + q*16, wfc2 + (size_t)n*768 + t*64 + q*8);
    }
}

__global__ __launch_bounds__(256) void mlp_fused(
    const __nv_bfloat16* __restrict__ xn,
    const __nv_bfloat16* __restrict__ wfc1, const float* __restrict__ fc1b,
    const __nv_bfloat16* __restrict__ wfc2, const float* __restrict__ fc2b,
    const float* __restrict__ res, float* __restrict__ out)
{
    extern __shared__ char smc[];
    int tid = threadIdx.x;
    int wid = tid >> 5, lane = tid & 31;
    int wm = wid >> 2, wn = wid & 3;
    int gid = lane >> 2, tig = lane & 3;
    int l2 = lane & 15;
    int row0 = blockIdx.x * 128;

    float acc2[4][6][4];
#pragma unroll
    for (int mi = 0; mi < 4; mi++)
#pragma unroll
        for (int ni = 0; ni < 6; ni++)
#pragma unroll
            for (int j = 0; j < 4; j++) acc2[mi][ni][j] = 0.f;

#pragma unroll
    for (int i = 0; i < 12; i++) {
        int idx = tid + i*256;
        int r = idx / 24, q = idx % 24;
        cp_async16(smc + MSX + r*400 + q*16, xn + (size_t)(row0 + r)*192 + q*8);
    }
    mlp_stage_b(smc, wfc1, wfc2, 0, tid);
    cp_commit();
    mlp_stage_b(smc, wfc1, wfc2, 1, tid);
    cp_commit();

    uint32_t sbase = (uint32_t)__cvta_generic_to_shared(smc);
    uint32_t aX  = sbase + MSX + (wm*64 + (lane & 7) + ((lane >> 3) & 1)*8)*400
                   + ((lane >> 4) & 1)*16;
    uint32_t aH  = sbase + MSH + (wm*64 + (lane & 7) + ((lane >> 3) & 1)*8)*144
                   + ((lane >> 4) & 1)*16;

    for (int t = 0; t < 12; t++) {
        if (t < 11) cp_wait<1>(); else cp_wait<0>();
        __syncthreads();
        int buf = t & 1;

        uint32_t bB1 = sbase + MSB1 + buf*25600
                     + (wn*16 + (l2 & 7))*400 + ((l2 >> 3) & 1)*16;
        float acc1[4][2][4];
#pragma unroll
        for (int mi = 0; mi < 4; mi++)
#pragma unroll
            for (int nj = 0; nj < 2; nj++)
#pragma unroll
                for (int j = 0; j < 4; j++) acc1[mi][nj][j] = 0.f;
#pragma unroll
        for (int ks = 0; ks < 12; ks++) {
            uint32_t av[4][4], bv[2][2];
#pragma unroll
            for (int mi = 0; mi < 4; mi++)
                ldsm_x4(av[mi], aX + mi*16*400 + ks*32);
#pragma unroll
            for (int nj = 0; nj < 2; nj++)
                ldsm_x2(bv[nj], bB1 + nj*8*400 + ks*32);
#pragma unroll
            for (int nj = 0; nj < 2; nj++)
#pragma unroll
                for (int mi = 0; mi < 4; mi++)
                    mma_bf16(acc1[mi][nj], av[mi], bv[nj][0], bv[nj][1]);
        }
#pragma unroll
        for (int mi = 0; mi < 4; mi++) {
            int r0 = wm*64 + mi*16 + gid;
#pragma unroll
            for (int nj = 0; nj < 2; nj++) {
                int colh = wn*16 + nj*8 + 2*tig;
                float2 bb = *(const float2*)&fc1b[t*64 + colh];
                __nv_bfloat162 p0 = __floats2bfloat162_rn(
                    gelu_exact(acc1[mi][nj][0] + bb.x),
                    gelu_exact(acc1[mi][nj][1] + bb.y));
                __nv_bfloat162 p1 = __floats2bfloat162_rn(
                    gelu_exact(acc1[mi][nj][2] + bb.x),
                    gelu_exact(acc1[mi][nj][3] + bb.y));
                *(__nv_bfloat162*)(smc + MSH + r0*144 + colh*2) = p0;
                *(__nv_bfloat162*)(smc + MSH + (r0+8)*144 + colh*2) = p1;
            }
        }
        __syncthreads();

        uint32_t bB2 = sbase + MSB2 + buf*27648
                     + (wn*48 + (l2 & 7))*144 + ((l2 >> 3) & 1)*16;
#pragma unroll
        for (int ks = 0; ks < 4; ks++) {
            uint32_t av[4][4], bv[6][2];
#pragma unroll
            for (int mi = 0; mi < 4; mi++)
                ldsm_x4(av[mi], aH + mi*16*144 + ks*32);
#pragma unroll
            for (int ni = 0; ni < 6; ni++)
                ldsm_x2(bv[ni], bB2 + ni*8*144 + ks*32);
#pragma unroll
            for (int ni = 0; ni < 6; ni++)
#pragma unroll
                for (int mi = 0; mi < 4; mi++)
                    mma_bf16(acc2[mi][ni], av[mi], bv[ni][0], bv[ni][1]);
        }
        __syncthreads();
        if (t + 2 < 12) {
            mlp_stage_b(smc, wfc1, wfc2, t + 2, tid);
            cp_commit();
        }
    }

#pragma unroll
    for (int mi = 0; mi < 4; mi++) {
        int r0 = row0 + wm*64 + mi*16 + gid;
#pragma unroll
        for (int ni = 0; ni < 6; ni++) {
            int col = wn*48 + ni*8 + 2*tig;
            float2 bb = *(const float2*)&fc2b[col];
            size_t o0 = (size_t)r0*192 + col;
            size_t o1 = (size_t)(r0 + 8)*192 + col;
            float2 r0v = *(const float2*)&res[o0];
            float2 r1v = *(const float2*)&res[o1];
            *(float2*)&out[o0] = make_float2(acc2[mi][ni][0] + bb.x + r0v.x,
                                             acc2[mi][ni][1] + bb.y + r0v.y);
            *(float2*)&out[o1] = make_float2(acc2[mi][ni][2] + bb.x + r1v.x,
                                             acc2[mi][ni][3] + bb.y + r1v.y);
        }
    }
}

// ---------------------------------------------------------------------------
// Attention core v3: mma.sync flash-style, one 128-thread block per
// (window, head). S = Q@K^T in tensor cores; softmax in C-fragment registers
// (cols >= 49 masked to -inf); P converted in-register to A-fragments; PV via
// MMA against transposed V^T tile. Scale applied to fp32 scores.
// ---------------------------------------------------------------------------
#define QST 40   // bf16 stride for Q,K rows (80B, ldmatrix conflict-free)
#define VST 72   // bf16 stride for V^T rows (144B, conflict-free)

__global__ __launch_bounds__(128) void attn_mma(
    const __nv_bfloat16* __restrict__ qkv, __nv_bfloat16* __restrict__ aout)
{
    __shared__ __nv_bfloat16 sQ[64*QST];
    __shared__ __nv_bfloat16 sK[64*QST];
    __shared__ __nv_bfloat16 sVT[32*VST];

    int widx = blockIdx.x;
    int head = blockIdx.y;
    int b  = widx >> 6;
    int wi = (widx >> 3) & 7;
    int wj = widx & 7;
    int tid  = threadIdx.x;
    int warp = tid >> 5, lane = tid & 31;
    int gid = lane >> 2, tig = lane & 3, l2 = lane & 15;
    const float scale = 0.17677669529663687f;  // 32^-0.5
    const __nv_bfloat16 bz = __float2bfloat16(0.f);

    // zero-fill padding: Q/K rows 49..63, V^T cols 49..63
    for (int i = tid; i < 15*QST; i += 128) {
        sQ[49*QST + i] = bz;
        sK[49*QST + i] = bz;
    }
    for (int i = tid; i < 32*15; i += 128) {
        int d = i / 15, c = 49 + i % 15;
        sVT[d*VST + c] = bz;
    }

    // gather 49 tokens (q,k row-major; v transposed)
    for (int idx = tid; idx < NTOK*4; idx += 128) {
        int n = idx >> 2, d8 = (idx & 3) << 3;
        int h  = (n/7)*8 + wi;
        int w2 = (n%7)*8 + wj;
        const __nv_bfloat16* bp =
            qkv + ((size_t)((b*HH + h)*WW) + w2)*576 + head*32 + d8;
        uint4 qv = *(const uint4*)bp;
        uint4 kv = *(const uint4*)(bp + 192);
        uint4 vv = *(const uint4*)(bp + 384);
        *(uint4*)&sQ[n*QST + d8] = qv;
        *(uint4*)&sK[n*QST + d8] = kv;
        __nv_bfloat16 vt[8];
        *(uint4*)vt = vv;
#pragma unroll
        for (int j = 0; j < 8; j++) sVT[(d8 + j)*VST + n] = vt[j];
    }
    __syncthreads();

    uint32_t qb = (uint32_t)__cvta_generic_to_shared(sQ);
    uint32_t kb = (uint32_t)__cvta_generic_to_shared(sK);
    uint32_t vb = (uint32_t)__cvta_generic_to_shared(sVT);

    int m0 = warp*16;
    uint32_t aQ = qb + (uint32_t)((m0 + (lane & 7) + ((lane >> 3) & 1)*8)*80
                                  + ((lane >> 4) & 1)*16);
    uint32_t bK = kb + (uint32_t)((l2 & 7)*80 + ((l2 >> 3) & 1)*16);
    uint32_t bV = vb + (uint32_t)((l2 & 7)*144 + ((l2 >> 3) & 1)*16);

    // ---- scores: S[16 rows][64 cols] per warp ----
    float sacc[8][4];
#pragma unroll
    for (int nt = 0; nt < 8; nt++)
#pragma unroll
        for (int j = 0; j < 4; j++) sacc[nt][j] = 0.f;
#pragma unroll
    for (int ks = 0; ks < 2; ks++) {
        uint32_t av[4];
        ldsm_x4(av, aQ + ks*32);
#pragma unroll
        for (int nt = 0; nt < 8; nt++) {
            uint32_t bv[2];
            ldsm_x2(bv, bK + nt*8*80 + ks*32);
            mma_bf16(sacc[nt], av, bv[0], bv[1]);
        }
    }

    // ---- softmax in registers (rows m0+gid and m0+gid+8) ----
    const float NEG = -1e30f;
    float rmax0 = NEG, rmax1 = NEG;
#pragma unroll
    for (int nt = 0; nt < 8; nt++) {
        int c0 = nt*8 + 2*tig;
        bool v0 = c0 < NTOK, v1 = (c0 + 1) < NTOK;
        sacc[nt][0] = v0 ? sacc[nt][0]*scale : NEG;
        sacc[nt][1] = v1 ? sacc[nt][1]*scale : NEG;
        sacc[nt][2] = v0 ? sacc[nt][2]*scale : NEG;
        sacc[nt][3] = v1 ? sacc[nt][3]*scale : NEG;
        rmax0 = fmaxf(rmax0, fmaxf(sacc[nt][0], sacc[nt][1]));
        rmax1 = fmaxf(rmax1, fmaxf(sacc[nt][2], sacc[nt][3]));
    }
    rmax0 = fmaxf(rmax0, __shfl_xor_sync(0xffffffffu, rmax0, 1));
    rmax0 = fmaxf(rmax0, __shfl_xor_sync(0xffffffffu, rmax0, 2));
    rmax1 = fmaxf(rmax1, __shfl_xor_sync(0xffffffffu, rmax1, 1));
    rmax1 = fmaxf(rmax1, __shfl_xor_sync(0xffffffffu, rmax1, 2));
    float rsum0 = 0.f, rsum1 = 0.f;
#pragma unroll
    for (int nt = 0; nt < 8; nt++) {
        sacc[nt][0] = expf(sacc[nt][0] - rmax0);
        sacc[nt][1] = expf(sacc[nt][1] - rmax0);
        sacc[nt][2] = expf(sacc[nt][2] - rmax1);
        sacc[nt][3] = expf(sacc[nt][3] - rmax1);
        rsum0 += sacc[nt][0] + sacc[nt][1];
        rsum1 += sacc[nt][2] + sacc[nt][3];
    }
    rsum0 += __shfl_xor_sync(0xffffffffu, rsum0, 1);
    rsum0 += __shfl_xor_sync(0xffffffffu, rsum0, 2);
    rsum1 += __shfl_xor_sync(0xffffffffu, rsum1, 1);
    rsum1 += __shfl_xor_sync(0xffffffffu, rsum1, 2);
    float inv0 = 1.f / rsum0, inv1 = 1.f / rsum1;

    // ---- PV: out[16][32] per warp; P regs -> A fragments directly ----
    float oacc[4][4];
#pragma unroll
    for (int nd = 0; nd < 4; nd++)
#pragma unroll
        for (int j = 0; j < 4; j++) oacc[nd][j] = 0.f;
#pragma unroll
    for (int s = 0; s < 4; s++) {
        uint32_t av[4];
        __nv_bfloat162 t;
        t = __floats2bfloat162_rn(sacc[2*s][0]*inv0, sacc[2*s][1]*inv0);
        av[0] = *(uint32_t*)&t;
        t = __floats2bfloat162_rn(sacc[2*s][2]*inv1, sacc[2*s][3]*inv1);
        av[1] = *(uint32_t*)&t;
        t = __floats2bfloat162_rn(sacc[2*s+1][0]*inv0, sacc[2*s+1][1]*inv0);
        av[2] = *(uint32_t*)&t;
        t = __floats2bfloat162_rn(sacc[2*s+1][2]*inv1, sacc[2*s+1][3]*inv1);
        av[3] = *(uint32_t*)&t;
#pragma unroll
        for (int nd = 0; nd < 4; nd++) {
            uint32_t bv[2];
            ldsm_x2(bv, bV + nd*8*144 + s*32);
            mma_bf16(oacc[nd], av, bv[0], bv[1]);
        }
    }

    // ---- store (only valid token rows) ----
#pragma unroll
    for (int r = 0; r < 2; r++) {
        int m = m0 + gid + r*8;
        if (m < NTOK) {
            int h  = (m/7)*8 + wi;
            int w2 = (m%7)*8 + wj;
            __nv_bfloat16* op =
                aout + ((size_t)((b*HH + h)*WW) + w2)*CC + head*HDIM;
#pragma unroll
            for (int nd = 0; nd < 4; nd++) {
                __nv_bfloat162 pv = __floats2bfloat162_rn(oacc[nd][2*r],
                                                          oacc[nd][2*r + 1]);
                *(__nv_bfloat162*)&op[nd*8 + 2*tig] = pv;
            }
        }
    }
}

// ---------------------------------------------------------------------------
extern "C" void kernel_launch(void* const* d_in, const int* in_sizes, int n_in,
                              void* d_out, int out_size)
{
    int p = 0;
    const float* x = (const float*)d_in[p++];
    while (p < n_in && in_sizes[p] == 1) p++;   // skip scalar H, W if present
    const float* cpe0_w = (const float*)d_in[p++];
    const float* cpe0_b = (const float*)d_in[p++];
    const float* cpe1_w = (const float*)d_in[p++];
    const float* cpe1_b = (const float*)d_in[p++];
    const float* n1_g   = (const float*)d_in[p++];
    const float* n1_b   = (const float*)d_in[p++];
    const float* qkv_w  = (const float*)d_in[p++];
    const float* qkv_b  = (const float*)d_in[p++];
    const float* proj_w = (const float*)d_in[p++];
    const float* proj_b = (const float*)d_in[p++];
    const float* n2_g   = (const float*)d_in[p++];
    const float* n2_b   = (const float*)d_in[p++];
    const float* fc1_w  = (const float*)d_in[p++];
    const float* fc1_b  = (const float*)d_in[p++];
    const float* fc2_w  = (const float*)d_in[p++];
    const float* fc2_b  = (const float*)d_in[p++];

    float *b0, *b1, *b2, *bqkv;
    __nv_bfloat16 *xn, *attn, *qkv, *wqkv, *wproj, *wfc1, *wfc2;
    cudaGetSymbolAddress((void**)&b0, g_buf0);
    cudaGetSymbolAddress((void**)&b1, g_buf1);
    cudaGetSymbolAddress((void**)&b2, g_buf2);
    cudaGetSymbolAddress((void**)&xn, g_xn);
    cudaGetSymbolAddress((void**)&attn, g_attn);
    cudaGetSymbolAddress((void**)&qkv, g_qkv);
    cudaGetSymbolAddress((void**)&wqkv, g_wqkv);
    cudaGetSymbolAddress((void**)&bqkv, g_bqkv);
    cudaGetSymbolAddress((void**)&wproj, g_wproj);
    cudaGetSymbolAddress((void**)&wfc1, g_wfc1);
    cudaGetSymbolAddress((void**)&wfc2, g_wfc2);

    cudaFuncSetAttribute(gemm_bf16<192,3>,
                         cudaFuncAttributeMaxDynamicSharedMemorySize, GEMM_SMEM_BYTES);
    cudaFuncSetAttribute(gemm_bf16<192,2>,
                         cudaFuncAttributeMaxDynamicSharedMemorySize, GEMM_SMEM_BYTES);
    cudaFuncSetAttribute(mlp_fused,
                         cudaFuncAttributeMaxDynamicSharedMemorySize, MLP_SMEM);

    dim3 gcpe(HH, BATCH);
    const int MB = TOKENS/128;   // 784

    prep_weights<<<dim3(576, 4), 256>>>(qkv_w, qkv_b, proj_w, fc1_w, fc2_w,
                                        wqkv, bqkv, wproj, wfc1, wfc2);
    cpe_kernel<<<gcpe, CC>>>(x, cpe0_w, cpe0_b, b0);
    ln_kernel<<<TOKENS/8, 256>>>(b0, n1_g, n1_b, xn);
    gemm_bf16<192,3><<<dim3(3, MB), 256, GEMM_SMEM_BYTES>>>(
        xn, wqkv, bqkv, nullptr, qkv, 576);
    attn_mma<<<dim3(BATCH*64, NHEAD), 128>>>(qkv, attn);
    gemm_bf16<192,2><<<dim3(1, MB), 256, GEMM_SMEM_BYTES>>>(
        attn, wproj, proj_b, b0, b1, 192);
    cpe_kernel<<<gcpe, CC>>>(b1, cpe1_w, cpe1_b, b2);
    ln_kernel<<<TOKENS/8, 256>>>(b2, n2_g, n2_b, xn);
    mlp_fused<<<MB, 256, MLP_SMEM>>>(xn, wfc1, fc1_b, wfc2, fc2_b,
                                     b2, (float*)d_out);
}

// round 14
// speedup vs baseline: 1.0624x; 1.0624x over previous
#include <cuda_runtime.h>
#include <cuda_bf16.h>
#include <math.h>
#include <stdint.h>

#define BATCH 32
#define HH 56
#define WW 56
#define CC 192
#define NHEAD 6
#define HDIM 32
#define NTOK 49
#define HIDDEN 768
#define TOKENS (BATCH*HH*WW)   // 100352

// Scratch (device globals — no runtime allocation allowed)
__device__ float g_buf0[TOKENS*CC];             // shortcut (after cpe0)
__device__ float g_buf1[TOKENS*CC];             // y (after attn residual)
__device__ float g_buf2[TOKENS*CC];             // y2 (after cpe1)
__device__ __nv_bfloat16 g_xn  [TOKENS*CC];     // LN output (bf16)
__device__ __nv_bfloat16 g_attn[TOKENS*CC];     // attention output (bf16)
__device__ __nv_bfloat16 g_qkv [TOKENS*3*CC];   // qkv bf16 [tok][kqv][head][32]
__device__ __nv_bfloat16 g_wqkv[576*192];       // [N][K] bf16
__device__ float        g_bqkv[576];
__device__ __nv_bfloat16 g_wproj[192*192];
__device__ __nv_bfloat16 g_wfc1[768*192];
__device__ __nv_bfloat16 g_wfc2[192*768];

__device__ __forceinline__ float gelu_exact(float x) {
    return 0.5f * x * (1.f + erff(x * 0.7071067811865475f));
}
__device__ __forceinline__ void cp_async16(void* smem, const void* gmem) {
    unsigned s = (unsigned)__cvta_generic_to_shared(smem);
    asm volatile("cp.async.cg.shared.global [%0], [%1], 16;" :: "r"(s), "l"(gmem));
}
__device__ __forceinline__ void cp_commit() {
    asm volatile("cp.async.commit_group;");
}
template<int N> __device__ __forceinline__ void cp_wait() {
    asm volatile("cp.async.wait_group %0;" :: "n"(N));
}
__device__ __forceinline__ void ldsm_x4(uint32_t* r, uint32_t addr) {
    asm volatile("ldmatrix.sync.aligned.m8n8.x4.shared.b16 {%0,%1,%2,%3}, [%4];"
        : "=r"(r[0]), "=r"(r[1]), "=r"(r[2]), "=r"(r[3]) : "r"(addr));
}
__device__ __forceinline__ void ldsm_x2(uint32_t* r, uint32_t addr) {
    asm volatile("ldmatrix.sync.aligned.m8n8.x2.shared.b16 {%0,%1}, [%2];"
        : "=r"(r[0]), "=r"(r[1]) : "r"(addr));
}
__device__ __forceinline__ void mma_bf16(float* c, const uint32_t* a,
                                         uint32_t b0, uint32_t b1) {
    asm volatile(
        "mma.sync.aligned.m16n8k16.row.col.f32.bf16.bf16.f32 "
        "{%0,%1,%2,%3}, {%4,%5,%6,%7}, {%8,%9}, {%0,%1,%2,%3};"
        : "+f"(c[0]), "+f"(c[1]), "+f"(c[2]), "+f"(c[3])
        : "r"(a[0]), "r"(a[1]), "r"(a[2]), "r"(a[3]), "r"(b0), "r"(b1));
}

// ---------------------------------------------------------------------------
// One-shot weight prep (4 jobs merged): W[K][N] -> Wt[N][K], bf16.
// Job 0 also applies the faithful (d k h) qkv column permutation.
// ---------------------------------------------------------------------------
__global__ void prep_weights(
    const float* __restrict__ qkv_w, const float* __restrict__ qkv_b,
    const float* __restrict__ proj_w, const float* __restrict__ fc1_w,
    const float* __restrict__ fc2_w,
    __nv_bfloat16* __restrict__ wqkv, float* __restrict__ bqkv,
    __nv_bfloat16* __restrict__ wproj, __nv_bfloat16* __restrict__ wfc1,
    __nv_bfloat16* __restrict__ wfc2)
{
    int job = blockIdx.y;
    int idx = blockIdx.x*256 + threadIdx.x;
    if (job == 0) {
        if (idx >= 576*192) return;
        int n = idx / 192, k = idx % 192;
        int kk = n / 192;
        int rem = n % 192;
        int h = rem / 32, d = rem % 32;
        int src = d*18 + kk*6 + h;
        wqkv[idx] = __float2bfloat16(qkv_w[(size_t)k*576 + src]);
        if (k == 0) bqkv[n] = qkv_b[src];
    } else if (job == 1) {
        if (idx >= 192*192) return;
        int n = idx / 192, k = idx % 192;
        wproj[idx] = __float2bfloat16(proj_w[(size_t)k*192 + n]);
    } else if (job == 2) {
        if (idx >= 768*192) return;
        int n = idx / 192, k = idx % 192;
        wfc1[idx] = __float2bfloat16(fc1_w[(size_t)k*768 + n]);
    } else {
        if (idx >= 192*768) return;
        int n = idx / 768, k = idx % 768;
        wfc2[idx] = __float2bfloat16(fc2_w[(size_t)k*192 + n]);
    }
}

// ---------------------------------------------------------------------------
// Depthwise 3x3 conv (SAME) + residual
// ---------------------------------------------------------------------------
__global__ void cpe_kernel(const float* __restrict__ in,
                           const float* __restrict__ wgt,
                           const float* __restrict__ bias,
                           float* __restrict__ out)
{
    int h = blockIdx.x;
    int b = blockIdx.y;
    int c = threadIdx.x;
    float kw[9];
#pragma unroll
    for (int i = 0; i < 9; i++) kw[i] = wgt[c*9 + i];
    float bb = bias[c];
    const float* base  = in  + ((size_t)b*HH*WW)*CC + c;
    float*       obase = out + ((size_t)b*HH*WW)*CC + c;

    float colL[3], colM[3], colR[3];
#pragma unroll
    for (int dy = 0; dy < 3; dy++) {
        colL[dy] = 0.f;
        int hy = h + dy - 1;
        colM[dy] = (hy >= 0 && hy < HH) ? base[(size_t)(hy*WW)*CC] : 0.f;
    }
    for (int x = 0; x < WW; x++) {
#pragma unroll
        for (int dy = 0; dy < 3; dy++) {
            int hy = h + dy - 1;
            colR[dy] = (x+1 < WW && hy >= 0 && hy < HH)
                       ? base[(size_t)(hy*WW + x + 1)*CC] : 0.f;
        }
        float acc = bb;
#pragma unroll
        for (int dy = 0; dy < 3; dy++) {
            acc = fmaf(kw[dy*3+0], colL[dy], acc);
            acc = fmaf(kw[dy*3+1], colM[dy], acc);
            acc = fmaf(kw[dy*3+2], colR[dy], acc);
        }
        obase[(size_t)(h*WW + x)*CC] = colM[1] + acc;
#pragma unroll
        for (int dy = 0; dy < 3; dy++) { colL[dy] = colM[dy]; colM[dy] = colR[dy]; }
    }
}

// ---------------------------------------------------------------------------
// Per-token LayerNorm -> bf16 output (feeds GEMMs only)
// ---------------------------------------------------------------------------
__global__ void ln_kernel(const float* __restrict__ in,
                          const float* __restrict__ g, const float* __restrict__ b,
                          __nv_bfloat16* __restrict__ out)
{
    int tok  = blockIdx.x*8 + (threadIdx.x >> 5);
    int lane = threadIdx.x & 31;
    const float* p = in + (size_t)tok*CC;
    __nv_bfloat16* o = out + (size_t)tok*CC;
    float vals[6]; float s = 0.f;
#pragma unroll
    for (int u = 0; u < 6; u++) { vals[u] = p[lane + u*32]; s += vals[u]; }
#pragma unroll
    for (int off = 16; off; off >>= 1) s += __shfl_xor_sync(0xffffffffu, s, off);
    float m = s * (1.f/192.f);
    float vv = 0.f;
#pragma unroll
    for (int u = 0; u < 6; u++) { float d = vals[u]-m; vv += d*d; }
#pragma unroll
    for (int off = 16; off; off >>= 1) vv += __shfl_xor_sync(0xffffffffu, vv, off);
    float rs = rsqrtf(vv*(1.f/192.f) + 1e-5f);
#pragma unroll
    for (int u = 0; u < 6; u++) {
        int c = lane + u*32;
        o[c] = __float2bfloat16((vals[u]-m)*rs*g[c] + b[c]);
    }
}

// ---------------------------------------------------------------------------
// bf16 mma.sync GEMM v3: 128x96 block tile, 256 threads (8 warps 2x4),
// warp tile 64x24 -> acc 48 regs -> 2 CTAs/SM (16 warps, 2x latency hiding).
// MODE: 2 = fp32 out + residual; 3 = bf16 out.
// ---------------------------------------------------------------------------
#define ASTG 10240                 // 128*40*2 bytes per A stage
#define BSTG 7680                  // 96*40*2 bytes per B stage
#define GEMM_SMEM_BYTES (3*(ASTG+BSTG))   // 53760

__device__ __forceinline__ void stage_bf16(
    char* sA, char* sB, const __nv_bfloat16* A, const __nv_bfloat16* Wt,
    int row0, int col0, int k0, int KTOT, int tid)
{
#pragma unroll
    for (int i = 0; i < 2; i++) {                 // A: 128 rows x 4 quads = 512
        int idx = tid + i*256;
        int r = idx >> 2, q = idx & 3;
        cp_async16(sA + r*80 + q*16, A + (size_t)(row0 + r)*KTOT + k0 + q*8);
    }
#pragma unroll
    for (int i = 0; i < 2; i++) {                 // B: 96 rows x 4 quads = 384
        int idx = tid + i*256;
        if (idx < 384) {
            int n = idx >> 2, q = idx & 3;
            cp_async16(sB + n*80 + q*16, Wt + (size_t)(col0 + n)*KTOT + k0 + q*8);
        }
    }
}

template<int KTOT, int MODE>
__global__ __launch_bounds__(256, 2) void gemm_bf16(
    const __nv_bfloat16* __restrict__ A, const __nv_bfloat16* __restrict__ Wt,
    const float* __restrict__ bias, const float* __restrict__ res,
    void* __restrict__ outv, int N)
{
    extern __shared__ char smc[];
    const int NC = KTOT/32;
    int tid = threadIdx.x;
    int wid = tid >> 5, lane = tid & 31;
    int wm = wid >> 2, wn = wid & 3;           // warp grid 2x4
    int gid = lane >> 2, tig = lane & 3;
    int col0 = blockIdx.x * 96;                // col tiles fast -> A L2 reuse
    int row0 = blockIdx.y * 128;

    float acc[4][3][4];
#pragma unroll
    for (int mi = 0; mi < 4; mi++)
#pragma unroll
        for (int ni = 0; ni < 3; ni++)
#pragma unroll
            for (int j = 0; j < 4; j++) acc[mi][ni][j] = 0.f;

#pragma unroll
    for (int c = 0; c < 3; c++) {
        stage_bf16(smc + c*ASTG, smc + 3*ASTG + c*BSTG, A, Wt,
                   row0, col0, c*32, KTOT, tid);
        cp_commit();
    }

    uint32_t sbase = (uint32_t)__cvta_generic_to_shared(smc);
    uint32_t aOff = (uint32_t)((wm*64 + (lane & 7) + ((lane >> 3) & 1)*8)*80
                               + ((lane >> 4) & 1)*16);
    int l2 = lane & 15;
    uint32_t bOff = (uint32_t)(3*ASTG + (wn*24 + (l2 & 7))*80 + ((l2 >> 3) & 1)*16);

    for (int c = 0; c < NC; c++) {
        if (c + 3 <= NC) cp_wait<2>();
        else if (c + 2 == NC) cp_wait<1>();
        else cp_wait<0>();
        __syncthreads();
        int st = c % 3;
        uint32_t aB = sbase + st*ASTG + aOff;
        uint32_t bB = sbase + st*BSTG + bOff;
#pragma unroll
        for (int ks = 0; ks < 2; ks++) {
            uint32_t av[4][4], bv[3][2];
#pragma unroll
            for (int mi = 0; mi < 4; mi++)
                ldsm_x4(av[mi], aB + mi*16*80 + ks*32);
#pragma unroll
            for (int ni = 0; ni < 3; ni++)
                ldsm_x2(bv[ni], bB + ni*8*80 + ks*32);
#pragma unroll
            for (int ni = 0; ni < 3; ni++)
#pragma unroll
                for (int mi = 0; mi < 4; mi++)
                    mma_bf16(acc[mi][ni], av[mi], bv[ni][0], bv[ni][1]);
        }
        __syncthreads();
        if (c + 3 < NC) {
            stage_bf16(smc + st*ASTG, smc + 3*ASTG + st*BSTG, A, Wt,
                       row0, col0, (c + 3)*32, KTOT, tid);
            cp_commit();
        }
    }

#pragma unroll
    for (int mi = 0; mi < 4; mi++) {
        int r0 = row0 + wm*64 + mi*16 + gid;
#pragma unroll
        for (int ni = 0; ni < 3; ni++) {
            int col = col0 + wn*24 + ni*8 + 2*tig;
            float2 bb = *(const float2*)&bias[col];
            float v0x = acc[mi][ni][0] + bb.x, v0y = acc[mi][ni][1] + bb.y;
            float v1x = acc[mi][ni][2] + bb.x, v1y = acc[mi][ni][3] + bb.y;
            size_t o0 = (size_t)r0*N + col;
            size_t o1 = (size_t)(r0 + 8)*N + col;
            if (MODE == 3) {
                __nv_bfloat16* out = (__nv_bfloat16*)outv;
                __nv_bfloat162 p0 = __floats2bfloat162_rn(v0x, v0y);
                __nv_bfloat162 p1 = __floats2bfloat162_rn(v1x, v1y);
                *(__nv_bfloat162*)&out[o0] = p0;
                *(__nv_bfloat162*)&out[o1] = p1;
            } else {
                float* out = (float*)outv;
                float2 r0v = *(const float2*)&res[o0];
                float2 r1v = *(const float2*)&res[o1];
                v0x += r0v.x; v0y += r0v.y;
                v1x += r1v.x; v1y += r1v.y;
                *(float2*)&out[o0] = make_float2(v0x, v0y);
                *(float2*)&out[o1] = make_float2(v1x, v1y);
            }
        }
    }
}

// ---------------------------------------------------------------------------
// Fused MLP (round-9 proven 256-thread config)
// ---------------------------------------------------------------------------
#define MSX  0
#define MSB1 51200
#define MSH  (51200+51200)
#define MSB2 (51200+51200+18432)
#define MLP_SMEM 176128

__device__ __forceinline__ void mlp_stage_b(
    char* smc, const __nv_bfloat16* wfc1, const __nv_bfloat16* wfc2,
    int t, int tid)
{
    char* b1 = smc + MSB1 + (t & 1)*25600;
    char* b2 = smc + MSB2 + (t & 1)*27648;
#pragma unroll
    for (int i = 0; i < 6; i++) {
        int idx = tid + i*256;
        int n = idx / 24, q = idx % 24;
        cp_async16(b1 + n*400 + q*16, wfc1 + (size_t)(t*64 + n)*192 + q*8);
    }
#pragma unroll
    for (int i = 0; i < 6; i++) {
        int idx = tid + i*256;
        int n = idx >> 3, q = idx & 7;
        cp_async16(b2 + n*144 + q*16, wfc2 + (size_t)n*768 + t*64 + q*8);
    }
}

__global__ __launch_bounds__(256) void mlp_fused(
    const __nv_bfloat16* __restrict__ xn,
    const __nv_bfloat16* __restrict__ wfc1, const float* __restrict__ fc1b,
    const __nv_bfloat16* __restrict__ wfc2, const float* __restrict__ fc2b,
    const float* __restrict__ res, float* __restrict__ out)
{
    extern __shared__ char smc[];
    int tid = threadIdx.x;
    int wid = tid >> 5, lane = tid & 31;
    int wm = wid >> 2, wn = wid & 3;
    int gid = lane >> 2, tig = lane & 3;
    int l2 = lane & 15;
    int row0 = blockIdx.x * 128;

    float acc2[4][6][4];
#pragma unroll
    for (int mi = 0; mi < 4; mi++)
#pragma unroll
        for (int ni = 0; ni < 6; ni++)
#pragma unroll
            for (int j = 0; j < 4; j++) acc2[mi][ni][j] = 0.f;

#pragma unroll
    for (int i = 0; i < 12; i++) {
        int idx = tid + i*256;
        int r = idx / 24, q = idx % 24;
        cp_async16(smc + MSX + r*400 + q*16, xn + (size_t)(row0 + r)*192 + q*8);
    }
    mlp_stage_b(smc, wfc1, wfc2, 0, tid);
    cp_commit();
    mlp_stage_b(smc, wfc1, wfc2, 1, tid);
    cp_commit();

    uint32_t sbase = (uint32_t)__cvta_generic_to_shared(smc);
    uint32_t aX  = sbase + MSX + (wm*64 + (lane & 7) + ((lane >> 3) & 1)*8)*400
                   + ((lane >> 4) & 1)*16;
    uint32_t aH  = sbase + MSH + (wm*64 + (lane & 7) + ((lane >> 3) & 1)*8)*144
                   + ((lane >> 4) & 1)*16;

    for (int t = 0; t < 12; t++) {
        if (t < 11) cp_wait<1>(); else cp_wait<0>();
        __syncthreads();
        int buf = t & 1;

        uint32_t bB1 = sbase + MSB1 + buf*25600
                     + (wn*16 + (l2 & 7))*400 + ((l2 >> 3) & 1)*16;
        float acc1[4][2][4];
#pragma unroll
        for (int mi = 0; mi < 4; mi++)
#pragma unroll
            for (int nj = 0; nj < 2; nj++)
#pragma unroll
                for (int j = 0; j < 4; j++) acc1[mi][nj][j] = 0.f;
#pragma unroll
        for (int ks = 0; ks < 12; ks++) {
            uint32_t av[4][4], bv[2][2];
#pragma unroll
            for (int mi = 0; mi < 4; mi++)
                ldsm_x4(av[mi], aX + mi*16*400 + ks*32);
#pragma unroll
            for (int nj = 0; nj < 2; nj++)
                ldsm_x2(bv[nj], bB1 + nj*8*400 + ks*32);
#pragma unroll
            for (int nj = 0; nj < 2; nj++)
#pragma unroll
                for (int mi = 0; mi < 4; mi++)
                    mma_bf16(acc1[mi][nj], av[mi], bv[nj][0], bv[nj][1]);
        }
#pragma unroll
        for (int mi = 0; mi < 4; mi++) {
            int r0 = wm*64 + mi*16 + gid;
#pragma unroll
            for (int nj = 0; nj < 2; nj++) {
                int colh = wn*16 + nj*8 + 2*tig;
                float2 bb = *(const float2*)&fc1b[t*64 + colh];
                __nv_bfloat162 p0 = __floats2bfloat162_rn(
                    gelu_exact(acc1[mi][nj][0] + bb.x),
                    gelu_exact(acc1[mi][nj][1] + bb.y));
                __nv_bfloat162 p1 = __floats2bfloat162_rn(
                    gelu_exact(acc1[mi][nj][2] + bb.x),
                    gelu_exact(acc1[mi][nj][3] + bb.y));
                *(__nv_bfloat162*)(smc + MSH + r0*144 + colh*2) = p0;
                *(__nv_bfloat162*)(smc + MSH + (r0+8)*144 + colh*2) = p1;
            }
        }
        __syncthreads();

        uint32_t bB2 = sbase + MSB2 + buf*27648
                     + (wn*48 + (l2 & 7))*144 + ((l2 >> 3) & 1)*16;
#pragma unroll
        for (int ks = 0; ks < 4; ks++) {
            uint32_t av[4][4], bv[6][2];
#pragma unroll
            for (int mi = 0; mi < 4; mi++)
                ldsm_x4(av[mi], aH + mi*16*144 + ks*32);
#pragma unroll
            for (int ni = 0; ni < 6; ni++)
                ldsm_x2(bv[ni], bB2 + ni*8*144 + ks*32);
#pragma unroll
            for (int ni = 0; ni < 6; ni++)
#pragma unroll
                for (int mi = 0; mi < 4; mi++)
                    mma_bf16(acc2[mi][ni], av[mi], bv[ni][0], bv[ni][1]);
        }
        __syncthreads();
        if (t + 2 < 12) {
            mlp_stage_b(smc, wfc1, wfc2, t + 2, tid);
            cp_commit();
        }
    }

#pragma unroll
    for (int mi = 0; mi < 4; mi++) {
        int r0 = row0 + wm*64 + mi*16 + gid;
#pragma unroll
        for (int ni = 0; ni < 6; ni++) {
            int col = wn*48 + ni*8 + 2*tig;
            float2 bb = *(const float2*)&fc2b[col];
            size_t o0 = (size_t)r0*192 + col;
            size_t o1 = (size_t)(r0 + 8)*192 + col;
            float2 r0v = *(const float2*)&res[o0];
            float2 r1v = *(const float2*)&res[o1];
            *(float2*)&out[o0] = make_float2(acc2[mi][ni][0] + bb.x + r0v.x,
                                             acc2[mi][ni][1] + bb.y + r0v.y);
            *(float2*)&out[o1] = make_float2(acc2[mi][ni][2] + bb.x + r1v.x,
                                             acc2[mi][ni][3] + bb.y + r1v.y);
        }
    }
}

// ---------------------------------------------------------------------------
// Attention core v3 (round-13 proven): mma.sync flash-style,
// one 128-thread block per (window, head).
// ---------------------------------------------------------------------------
#define QST 40
#define VST 72

__global__ __launch_bounds__(128) void attn_mma(
    const __nv_bfloat16* __restrict__ qkv, __nv_bfloat16* __restrict__ aout)
{
    __shared__ __nv_bfloat16 sQ[64*QST];
    __shared__ __nv_bfloat16 sK[64*QST];
    __shared__ __nv_bfloat16 sVT[32*VST];

    int widx = blockIdx.x;
    int head = blockIdx.y;
    int b  = widx >> 6;
    int wi = (widx >> 3) & 7;
    int wj = widx & 7;
    int tid  = threadIdx.x;
    int warp = tid >> 5, lane = tid & 31;
    int gid = lane >> 2, tig = lane & 3, l2 = lane & 15;
    const float scale = 0.17677669529663687f;
    const __nv_bfloat16 bz = __float2bfloat16(0.f);

    for (int i = tid; i < 15*QST; i += 128) {
        sQ[49*QST + i] = bz;
        sK[49*QST + i] = bz;
    }
    for (int i = tid; i < 32*15; i += 128) {
        int d = i / 15, c = 49 + i % 15;
        sVT[d*VST + c] = bz;
    }

    for (int idx = tid; idx < NTOK*4; idx += 128) {
        int n = idx >> 2, d8 = (idx & 3) << 3;
        int h  = (n/7)*8 + wi;
        int w2 = (n%7)*8 + wj;
        const __nv_bfloat16* bp =
            qkv + ((size_t)((b*HH + h)*WW) + w2)*576 + head*32 + d8;
        uint4 qv = *(const uint4*)bp;
        uint4 kv = *(const uint4*)(bp + 192);
        uint4 vv = *(const uint4*)(bp + 384);
        *(uint4*)&sQ[n*QST + d8] = qv;
        *(uint4*)&sK[n*QST + d8] = kv;
        __nv_bfloat16 vt[8];
        *(uint4*)vt = vv;
#pragma unroll
        for (int j = 0; j < 8; j++) sVT[(d8 + j)*VST + n] = vt[j];
    }
    __syncthreads();

    uint32_t qb = (uint32_t)__cvta_generic_to_shared(sQ);
    uint32_t kb = (uint32_t)__cvta_generic_to_shared(sK);
    uint32_t vb = (uint32_t)__cvta_generic_to_shared(sVT);

    int m0 = warp*16;
    uint32_t aQ = qb + (uint32_t)((m0 + (lane & 7) + ((lane >> 3) & 1)*8)*80
                                  + ((lane >> 4) & 1)*16);
    uint32_t bK = kb + (uint32_t)((l2 & 7)*80 + ((l2 >> 3) & 1)*16);
    uint32_t bV = vb + (uint32_t)((l2 & 7)*144 + ((l2 >> 3) & 1)*16);

    float sacc[8][4];
#pragma unroll
    for (int nt = 0; nt < 8; nt++)
#pragma unroll
        for (int j = 0; j < 4; j++) sacc[nt][j] = 0.f;
#pragma unroll
    for (int ks = 0; ks < 2; ks++) {
        uint32_t av[4];
        ldsm_x4(av, aQ + ks*32);
#pragma unroll
        for (int nt = 0; nt < 8; nt++) {
            uint32_t bv[2];
            ldsm_x2(bv, bK + nt*8*80 + ks*32);
            mma_bf16(sacc[nt], av, bv[0], bv[1]);
        }
    }

    const float NEG = -1e30f;
    float rmax0 = NEG, rmax1 = NEG;
#pragma unroll
    for (int nt = 0; nt < 8; nt++) {
        int c0 = nt*8 + 2*tig;
        bool v0 = c0 < NTOK, v1 = (c0 + 1) < NTOK;
        sacc[nt][0] = v0 ? sacc[nt][0]*scale : NEG;
        sacc[nt][1] = v1 ? sacc[nt][1]*scale : NEG;
        sacc[nt][2] = v0 ? sacc[nt][2]*scale : NEG;
        sacc[nt][3] = v1 ? sacc[nt][3]*scale : NEG;
        rmax0 = fmaxf(rmax0, fmaxf(sacc[nt][0], sacc[nt][1]));
        rmax1 = fmaxf(rmax1, fmaxf(sacc[nt][2], sacc[nt][3]));
    }
    rmax0 = fmaxf(rmax0, __shfl_xor_sync(0xffffffffu, rmax0, 1));
    rmax0 = fmaxf(rmax0, __shfl_xor_sync(0xffffffffu, rmax0, 2));
    rmax1 = fmaxf(rmax1, __shfl_xor_sync(0xffffffffu, rmax1, 1));
    rmax1 = fmaxf(rmax1, __shfl_xor_sync(0xffffffffu, rmax1, 2));
    float rsum0 = 0.f, rsum1 = 0.f;
#pragma unroll
    for (int nt = 0; nt < 8; nt++) {
        sacc[nt][0] = expf(sacc[nt][0] - rmax0);
        sacc[nt][1] = expf(sacc[nt][1] - rmax0);
        sacc[nt][2] = expf(sacc[nt][2] - rmax1);
        sacc[nt][3] = expf(sacc[nt][3] - rmax1);
        rsum0 += sacc[nt][0] + sacc[nt][1];
        rsum1 += sacc[nt][2] + sacc[nt][3];
    }
    rsum0 += __shfl_xor_sync(0xffffffffu, rsum0, 1);
    rsum0 += __shfl_xor_sync(0xffffffffu, rsum0, 2);
    rsum1 += __shfl_xor_sync(0xffffffffu, rsum1, 1);
    rsum1 += __shfl_xor_sync(0xffffffffu, rsum1, 2);
    float inv0 = 1.f / rsum0, inv1 = 1.f / rsum1;

    float oacc[4][4];
#pragma unroll
    for (int nd = 0; nd < 4; nd++)
#pragma unroll
        for (int j = 0; j < 4; j++) oacc[nd][j] = 0.f;
#pragma unroll
    for (int s = 0; s < 4; s++) {
        uint32_t av[4];
        __nv_bfloat162 t;
        t = __floats2bfloat162_rn(sacc[2*s][0]*inv0, sacc[2*s][1]*inv0);
        av[0] = *(uint32_t*)&t;
        t = __floats2bfloat162_rn(sacc[2*s][2]*inv1, sacc[2*s][3]*inv1);
        av[1] = *(uint32_t*)&t;
        t = __floats2bfloat162_rn(sacc[2*s+1][0]*inv0, sacc[2*s+1][1]*inv0);
        av[2] = *(uint32_t*)&t;
        t = __floats2bfloat162_rn(sacc[2*s+1][2]*inv1, sacc[2*s+1][3]*inv1);
        av[3] = *(uint32_t*)&t;
#pragma unroll
        for (int nd = 0; nd < 4; nd++) {
            uint32_t bv[2];
            ldsm_x2(bv, bV + nd*8*144 + s*32);
            mma_bf16(oacc[nd], av, bv[0], bv[1]);
        }
    }

#pragma unroll
    for (int r = 0; r < 2; r++) {
        int m = m0 + gid + r*8;
        if (m < NTOK) {
            int h  = (m/7)*8 + wi;
            int w2 = (m%7)*8 + wj;
            __nv_bfloat16* op =
                aout + ((size_t)((b*HH + h)*WW) + w2)*CC + head*HDIM;
#pragma unroll
            for (int nd = 0; nd < 4; nd++) {
                __nv_bfloat162 pv = __floats2bfloat162_rn(oacc[nd][2*r],
                                                          oacc[nd][2*r + 1]);
                *(__nv_bfloat162*)&op[nd*8 + 2*tig] = pv;
            }
        }
    }
}

// ---------------------------------------------------------------------------
extern "C" void kernel_launch(void* const* d_in, const int* in_sizes, int n_in,
                              void* d_out, int out_size)
{
    int p = 0;
    const float* x = (const float*)d_in[p++];
    while (p < n_in && in_sizes[p] == 1) p++;   // skip scalar H, W if present
    const float* cpe0_w = (const float*)d_in[p++];
    const float* cpe0_b = (const float*)d_in[p++];
    const float* cpe1_w = (const float*)d_in[p++];
    const float* cpe1_b = (const float*)d_in[p++];
    const float* n1_g   = (const float*)d_in[p++];
    const float* n1_b   = (const float*)d_in[p++];
    const float* qkv_w  = (const float*)d_in[p++];
    const float* qkv_b  = (const float*)d_in[p++];
    const float* proj_w = (const float*)d_in[p++];
    const float* proj_b = (const float*)d_in[p++];
    const float* n2_g   = (const float*)d_in[p++];
    const float* n2_b   = (const float*)d_in[p++];
    const float* fc1_w  = (const float*)d_in[p++];
    const float* fc1_b  = (const float*)d_in[p++];
    const float* fc2_w  = (const float*)d_in[p++];
    const float* fc2_b  = (const float*)d_in[p++];

    float *b0, *b1, *b2, *bqkv;
    __nv_bfloat16 *xn, *attn, *qkv, *wqkv, *wproj, *wfc1, *wfc2;
    cudaGetSymbolAddress((void**)&b0, g_buf0);
    cudaGetSymbolAddress((void**)&b1, g_buf1);
    cudaGetSymbolAddress((void**)&b2, g_buf2);
    cudaGetSymbolAddress((void**)&xn, g_xn);
    cudaGetSymbolAddress((void**)&attn, g_attn);
    cudaGetSymbolAddress((void**)&qkv, g_qkv);
    cudaGetSymbolAddress((void**)&wqkv, g_wqkv);
    cudaGetSymbolAddress((void**)&bqkv, g_bqkv);
    cudaGetSymbolAddress((void**)&wproj, g_wproj);
    cudaGetSymbolAddress((void**)&wfc1, g_wfc1);
    cudaGetSymbolAddress((void**)&wfc2, g_wfc2);

    cudaFuncSetAttribute(gemm_bf16<192,3>,
                         cudaFuncAttributeMaxDynamicSharedMemorySize, GEMM_SMEM_BYTES);
    cudaFuncSetAttribute(gemm_bf16<192,2>,
                         cudaFuncAttributeMaxDynamicSharedMemorySize, GEMM_SMEM_BYTES);
    cudaFuncSetAttribute(mlp_fused,
                         cudaFuncAttributeMaxDynamicSharedMemorySize, MLP_SMEM);

    dim3 gcpe(HH, BATCH);
    const int MB = TOKENS/128;   // 784

    prep_weights<<<dim3(576, 4), 256>>>(qkv_w, qkv_b, proj_w, fc1_w, fc2_w,
                                        wqkv, bqkv, wproj, wfc1, wfc2);
    cpe_kernel<<<gcpe, CC>>>(x, cpe0_w, cpe0_b, b0);
    ln_kernel<<<TOKENS/8, 256>>>(b0, n1_g, n1_b, xn);
    gemm_bf16<192,3><<<dim3(6, MB), 256, GEMM_SMEM_BYTES>>>(
        xn, wqkv, bqkv, nullptr, qkv, 576);
    attn_mma<<<dim3(BATCH*64, NHEAD), 128>>>(qkv, attn);
    gemm_bf16<192,2><<<dim3(2, MB), 256, GEMM_SMEM_BYTES>>>(
        attn, wproj, proj_b, b0, b1, 192);
    cpe_kernel<<<gcpe, CC>>>(b1, cpe1_w, cpe1_b, b2);
    ln_kernel<<<TOKENS/8, 256>>>(b2, n2_g, n2_b, xn);
    mlp_fused<<<MB, 256, MLP_SMEM>>>(xn, wfc1, fc1_b, wfc2, fc2_b,
                                     b2, (float*)d_out);
}

// round 15
// speedup vs baseline: 1.0625x; 1.0000x over previous
#include <cuda_runtime.h>
#include <cuda_bf16.h>
#include <math.h>
#include <stdint.h>

#define BATCH 32
#define HH 56
#define WW 56
#define CC 192
#define NHEAD 6
#define HDIM 32
#define NTOK 49
#define HIDDEN 768
#define TOKENS (BATCH*HH*WW)   // 100352

// Scratch (device globals — no runtime allocation allowed)
__device__ float g_buf0[TOKENS*CC];             // shortcut (after cpe0)
__device__ float g_buf1[TOKENS*CC];             // y (after attn residual)
__device__ float g_buf2[TOKENS*CC];             // y2 (after cpe1)
__device__ __nv_bfloat16 g_xn  [TOKENS*CC];     // LN output (bf16)
__device__ __nv_bfloat16 g_attn[TOKENS*CC];     // attention output (bf16)
__device__ __nv_bfloat16 g_qkv [TOKENS*3*CC];   // qkv bf16 [tok][kqv][head][32]
__device__ __nv_bfloat16 g_wqkv[576*192];       // [N][K] bf16
__device__ float        g_bqkv[576];
__device__ __nv_bfloat16 g_wproj[192*192];
__device__ __nv_bfloat16 g_wfc1[768*192];
__device__ __nv_bfloat16 g_wfc2[192*768];

__device__ __forceinline__ float gelu_exact(float x) {
    return 0.5f * x * (1.f + erff(x * 0.7071067811865475f));
}
__device__ __forceinline__ void cp_async16(void* smem, const void* gmem) {
    unsigned s = (unsigned)__cvta_generic_to_shared(smem);
    asm volatile("cp.async.cg.shared.global [%0], [%1], 16;" :: "r"(s), "l"(gmem));
}
__device__ __forceinline__ void cp_commit() {
    asm volatile("cp.async.commit_group;");
}
template<int N> __device__ __forceinline__ void cp_wait() {
    asm volatile("cp.async.wait_group %0;" :: "n"(N));
}
__device__ __forceinline__ void ldsm_x4(uint32_t* r, uint32_t addr) {
    asm volatile("ldmatrix.sync.aligned.m8n8.x4.shared.b16 {%0,%1,%2,%3}, [%4];"
        : "=r"(r[0]), "=r"(r[1]), "=r"(r[2]), "=r"(r[3]) : "r"(addr));
}
__device__ __forceinline__ void ldsm_x2(uint32_t* r, uint32_t addr) {
    asm volatile("ldmatrix.sync.aligned.m8n8.x2.shared.b16 {%0,%1}, [%2];"
        : "=r"(r[0]), "=r"(r[1]) : "r"(addr));
}
__device__ __forceinline__ void mma_bf16(float* c, const uint32_t* a,
                                         uint32_t b0, uint32_t b1) {
    asm volatile(
        "mma.sync.aligned.m16n8k16.row.col.f32.bf16.bf16.f32 "
        "{%0,%1,%2,%3}, {%4,%5,%6,%7}, {%8,%9}, {%0,%1,%2,%3};"
        : "+f"(c[0]), "+f"(c[1]), "+f"(c[2]), "+f"(c[3])
        : "r"(a[0]), "r"(a[1]), "r"(a[2]), "r"(a[3]), "r"(b0), "r"(b1));
}

// ---------------------------------------------------------------------------
// One-shot weight prep (4 jobs merged): W[K][N] -> Wt[N][K], bf16.
// Job 0 also applies the faithful (d k h) qkv column permutation.
// ---------------------------------------------------------------------------
__global__ void prep_weights(
    const float* __restrict__ qkv_w, const float* __restrict__ qkv_b,
    const float* __restrict__ proj_w, const float* __restrict__ fc1_w,
    const float* __restrict__ fc2_w,
    __nv_bfloat16* __restrict__ wqkv, float* __restrict__ bqkv,
    __nv_bfloat16* __restrict__ wproj, __nv_bfloat16* __restrict__ wfc1,
    __nv_bfloat16* __restrict__ wfc2)
{
    int job = blockIdx.y;
    int idx = blockIdx.x*256 + threadIdx.x;
    if (job == 0) {
        if (idx >= 576*192) return;
        int n = idx / 192, k = idx % 192;
        int kk = n / 192;
        int rem = n % 192;
        int h = rem / 32, d = rem % 32;
        int src = d*18 + kk*6 + h;
        wqkv[idx] = __float2bfloat16(qkv_w[(size_t)k*576 + src]);
        if (k == 0) bqkv[n] = qkv_b[src];
    } else if (job == 1) {
        if (idx >= 192*192) return;
        int n = idx / 192, k = idx % 192;
        wproj[idx] = __float2bfloat16(proj_w[(size_t)k*192 + n]);
    } else if (job == 2) {
        if (idx >= 768*192) return;
        int n = idx / 192, k = idx % 192;
        wfc1[idx] = __float2bfloat16(fc1_w[(size_t)k*768 + n]);
    } else {
        if (idx >= 192*768) return;
        int n = idx / 768, k = idx % 768;
        wfc2[idx] = __float2bfloat16(fc2_w[(size_t)k*192 + n]);
    }
}

// ---------------------------------------------------------------------------
// Depthwise 3x3 conv (SAME) + residual
// ---------------------------------------------------------------------------
__global__ void cpe_kernel(const float* __restrict__ in,
                           const float* __restrict__ wgt,
                           const float* __restrict__ bias,
                           float* __restrict__ out)
{
    int h = blockIdx.x;
    int b = blockIdx.y;
    int c = threadIdx.x;
    float kw[9];
#pragma unroll
    for (int i = 0; i < 9; i++) kw[i] = wgt[c*9 + i];
    float bb = bias[c];
    const float* base  = in  + ((size_t)b*HH*WW)*CC + c;
    float*       obase = out + ((size_t)b*HH*WW)*CC + c;

    float colL[3], colM[3], colR[3];
#pragma unroll
    for (int dy = 0; dy < 3; dy++) {
        colL[dy] = 0.f;
        int hy = h + dy - 1;
        colM[dy] = (hy >= 0 && hy < HH) ? base[(size_t)(hy*WW)*CC] : 0.f;
    }
    for (int x = 0; x < WW; x++) {
#pragma unroll
        for (int dy = 0; dy < 3; dy++) {
            int hy = h + dy - 1;
            colR[dy] = (x+1 < WW && hy >= 0 && hy < HH)
                       ? base[(size_t)(hy*WW + x + 1)*CC] : 0.f;
        }
        float acc = bb;
#pragma unroll
        for (int dy = 0; dy < 3; dy++) {
            acc = fmaf(kw[dy*3+0], colL[dy], acc);
            acc = fmaf(kw[dy*3+1], colM[dy], acc);
            acc = fmaf(kw[dy*3+2], colR[dy], acc);
        }
        obase[(size_t)(h*WW + x)*CC] = colM[1] + acc;
#pragma unroll
        for (int dy = 0; dy < 3; dy++) { colL[dy] = colM[dy]; colM[dy] = colR[dy]; }
    }
}

// ---------------------------------------------------------------------------
// Per-token LayerNorm -> bf16 output (feeds GEMMs only)
// ---------------------------------------------------------------------------
__global__ void ln_kernel(const float* __restrict__ in,
                          const float* __restrict__ g, const float* __restrict__ b,
                          __nv_bfloat16* __restrict__ out)
{
    int tok  = blockIdx.x*8 + (threadIdx.x >> 5);
    int lane = threadIdx.x & 31;
    const float* p = in + (size_t)tok*CC;
    __nv_bfloat16* o = out + (size_t)tok*CC;
    float vals[6]; float s = 0.f;
#pragma unroll
    for (int u = 0; u < 6; u++) { vals[u] = p[lane + u*32]; s += vals[u]; }
#pragma unroll
    for (int off = 16; off; off >>= 1) s += __shfl_xor_sync(0xffffffffu, s, off);
    float m = s * (1.f/192.f);
    float vv = 0.f;
#pragma unroll
    for (int u = 0; u < 6; u++) { float d = vals[u]-m; vv += d*d; }
#pragma unroll
    for (int off = 16; off; off >>= 1) vv += __shfl_xor_sync(0xffffffffu, vv, off);
    float rs = rsqrtf(vv*(1.f/192.f) + 1e-5f);
#pragma unroll
    for (int u = 0; u < 6; u++) {
        int c = lane + u*32;
        o[c] = __float2bfloat16((vals[u]-m)*rs*g[c] + b[c]);
    }
}

// ---------------------------------------------------------------------------
// bf16 mma.sync GEMM v3: 128x96 block tile, 256 threads (8 warps 2x4),
// warp tile 64x24 -> acc 48 regs -> 2 CTAs/SM (16 warps, 2x latency hiding).
// MODE: 2 = fp32 out + residual; 3 = bf16 out.
// ---------------------------------------------------------------------------
#define ASTG 10240                 // 128*40*2 bytes per A stage
#define BSTG 7680                  // 96*40*2 bytes per B stage
#define GEMM_SMEM_BYTES (3*(ASTG+BSTG))   // 53760

__device__ __forceinline__ void stage_bf16(
    char* sA, char* sB, const __nv_bfloat16* A, const __nv_bfloat16* Wt,
    int row0, int col0, int k0, int KTOT, int tid)
{
#pragma unroll
    for (int i = 0; i < 2; i++) {                 // A: 128 rows x 4 quads = 512
        int idx = tid + i*256;
        int r = idx >> 2, q = idx & 3;
        cp_async16(sA + r*80 + q*16, A + (size_t)(row0 + r)*KTOT + k0 + q*8);
    }
#pragma unroll
    for (int i = 0; i < 2; i++) {                 // B: 96 rows x 4 quads = 384
        int idx = tid + i*256;
        if (idx < 384) {
            int n = idx >> 2, q = idx & 3;
            cp_async16(sB + n*80 + q*16, Wt + (size_t)(col0 + n)*KTOT + k0 + q*8);
        }
    }
}

template<int KTOT, int MODE>
__global__ __launch_bounds__(256, 2) void gemm_bf16(
    const __nv_bfloat16* __restrict__ A, const __nv_bfloat16* __restrict__ Wt,
    const float* __restrict__ bias, const float* __restrict__ res,
    void* __restrict__ outv, int N)
{
    extern __shared__ char smc[];
    const int NC = KTOT/32;
    int tid = threadIdx.x;
    int wid = tid >> 5, lane = tid & 31;
    int wm = wid >> 2, wn = wid & 3;           // warp grid 2x4
    int gid = lane >> 2, tig = lane & 3;
    int col0 = blockIdx.x * 96;                // col tiles fast -> A L2 reuse
    int row0 = blockIdx.y * 128;

    float acc[4][3][4];
#pragma unroll
    for (int mi = 0; mi < 4; mi++)
#pragma unroll
        for (int ni = 0; ni < 3; ni++)
#pragma unroll
            for (int j = 0; j < 4; j++) acc[mi][ni][j] = 0.f;

#pragma unroll
    for (int c = 0; c < 3; c++) {
        stage_bf16(smc + c*ASTG, smc + 3*ASTG + c*BSTG, A, Wt,
                   row0, col0, c*32, KTOT, tid);
        cp_commit();
    }

    uint32_t sbase = (uint32_t)__cvta_generic_to_shared(smc);
    uint32_t aOff = (uint32_t)((wm*64 + (lane & 7) + ((lane >> 3) & 1)*8)*80
                               + ((lane >> 4) & 1)*16);
    int l2 = lane & 15;
    uint32_t bOff = (uint32_t)(3*ASTG + (wn*24 + (l2 & 7))*80 + ((l2 >> 3) & 1)*16);

    for (int c = 0; c < NC; c++) {
        if (c + 3 <= NC) cp_wait<2>();
        else if (c + 2 == NC) cp_wait<1>();
        else cp_wait<0>();
        __syncthreads();
        int st = c % 3;
        uint32_t aB = sbase + st*ASTG + aOff;
        uint32_t bB = sbase + st*BSTG + bOff;
#pragma unroll
        for (int ks = 0; ks < 2; ks++) {
            uint32_t av[4][4], bv[3][2];
#pragma unroll
            for (int mi = 0; mi < 4; mi++)
                ldsm_x4(av[mi], aB + mi*16*80 + ks*32);
#pragma unroll
            for (int ni = 0; ni < 3; ni++)
                ldsm_x2(bv[ni], bB + ni*8*80 + ks*32);
#pragma unroll
            for (int ni = 0; ni < 3; ni++)
#pragma unroll
                for (int mi = 0; mi < 4; mi++)
                    mma_bf16(acc[mi][ni], av[mi], bv[ni][0], bv[ni][1]);
        }
        __syncthreads();
        if (c + 3 < NC) {
            stage_bf16(smc + st*ASTG, smc + 3*ASTG + st*BSTG, A, Wt,
                       row0, col0, (c + 3)*32, KTOT, tid);
            cp_commit();
        }
    }

#pragma unroll
    for (int mi = 0; mi < 4; mi++) {
        int r0 = row0 + wm*64 + mi*16 + gid;
#pragma unroll
        for (int ni = 0; ni < 3; ni++) {
            int col = col0 + wn*24 + ni*8 + 2*tig;
            float2 bb = *(const float2*)&bias[col];
            float v0x = acc[mi][ni][0] + bb.x, v0y = acc[mi][ni][1] + bb.y;
            float v1x = acc[mi][ni][2] + bb.x, v1y = acc[mi][ni][3] + bb.y;
            size_t o0 = (size_t)r0*N + col;
            size_t o1 = (size_t)(r0 + 8)*N + col;
            if (MODE == 3) {
                __nv_bfloat16* out = (__nv_bfloat16*)outv;
                __nv_bfloat162 p0 = __floats2bfloat162_rn(v0x, v0y);
                __nv_bfloat162 p1 = __floats2bfloat162_rn(v1x, v1y);
                *(__nv_bfloat162*)&out[o0] = p0;
                *(__nv_bfloat162*)&out[o1] = p1;
            } else {
                float* out = (float*)outv;
                float2 r0v = *(const float2*)&res[o0];
                float2 r1v = *(const float2*)&res[o1];
                v0x += r0v.x; v0y += r0v.y;
                v1x += r1v.x; v1y += r1v.y;
                *(float2*)&out[o0] = make_float2(v0x, v0y);
                *(float2*)&out[o1] = make_float2(v1x, v1y);
            }
        }
    }
}

// ---------------------------------------------------------------------------
// Fused MLP (round-9 proven 256-thread config)
// ---------------------------------------------------------------------------
#define MSX  0
#define MSB1 51200
#define MSH  (51200+51200)
#define MSB2 (51200+51200+18432)
#define MLP_SMEM 176128

__device__ __forceinline__ void mlp_stage_b(
    char* smc, const __nv_bfloat16* wfc1, const __nv_bfloat16* wfc2,
    int t, int tid)
{
    char* b1 = smc + MSB1 + (t & 1)*25600;
    char* b2 = smc + MSB2 + (t & 1)*27648;
#pragma unroll
    for (int i = 0; i < 6; i++) {
        int idx = tid + i*256;
        int n = idx / 24, q = idx % 24;
        cp_async16(b1 + n*400 + q*16, wfc1 + (size_t)(t*64 + n)*192 + q*8);
    }
#pragma unroll
    for (int i = 0; i < 6; i++) {
        int idx = tid + i*256;
        int n = idx >> 3, q = idx & 7;
        cp_async16(b2 + n*144 + q*16, wfc2 + (size_t)n*768 + t*64 + q*8);
    }
}

__global__ __launch_bounds__(256) void mlp_fused(
    const __nv_bfloat16* __restrict__ xn,
    const __nv_bfloat16* __restrict__ wfc1, const float* __restrict__ fc1b,
    const __nv_bfloat16* __restrict__ wfc2, const float* __restrict__ fc2b,
    const float* __restrict__ res, float* __restrict__ out)
{
    extern __shared__ char smc[];
    int tid = threadIdx.x;
    int wid = tid >> 5, lane = tid & 31;
    int wm = wid >> 2, wn = wid & 3;
    int gid = lane >> 2, tig = lane & 3;
    int l2 = lane & 15;
    int row0 = blockIdx.x * 128;

    float acc2[4][6][4];
#pragma unroll
    for (int mi = 0; mi < 4; mi++)
#pragma unroll
        for (int ni = 0; ni < 6; ni++)
#pragma unroll
            for (int j = 0; j < 4; j++) acc2[mi][ni][j] = 0.f;

#pragma unroll
    for (int i = 0; i < 12; i++) {
        int idx = tid + i*256;
        int r = idx / 24, q = idx % 24;
        cp_async16(smc + MSX + r*400 + q*16, xn + (size_t)(row0 + r)*192 + q*8);
    }
    mlp_stage_b(smc, wfc1, wfc2, 0, tid);
    cp_commit();
    mlp_stage_b(smc, wfc1, wfc2, 1, tid);
    cp_commit();

    uint32_t sbase = (uint32_t)__cvta_generic_to_shared(smc);
    uint32_t aX  = sbase + MSX + (wm*64 + (lane & 7) + ((lane >> 3) & 1)*8)*400
                   + ((lane >> 4) & 1)*16;
    uint32_t aH  = sbase + MSH + (wm*64 + (lane & 7) + ((lane >> 3) & 1)*8)*144
                   + ((lane >> 4) & 1)*16;

    for (int t = 0; t < 12; t++) {
        if (t < 11) cp_wait<1>(); else cp_wait<0>();
        __syncthreads();
        int buf = t & 1;

        uint32_t bB1 = sbase + MSB1 + buf*25600
                     + (wn*16 + (l2 & 7))*400 + ((l2 >> 3) & 1)*16;
        float acc1[4][2][4];
#pragma unroll
        for (int mi = 0; mi < 4; mi++)
#pragma unroll
            for (int nj = 0; nj < 2; nj++)
#pragma unroll
                for (int j = 0; j < 4; j++) acc1[mi][nj][j] = 0.f;
#pragma unroll
        for (int ks = 0; ks < 12; ks++) {
            uint32_t av[4][4], bv[2][2];
#pragma unroll
            for (int mi = 0; mi < 4; mi++)
                ldsm_x4(av[mi], aX + mi*16*400 + ks*32);
#pragma unroll
            for (int nj = 0; nj < 2; nj++)
                ldsm_x2(bv[nj], bB1 + nj*8*400 + ks*32);
#pragma unroll
            for (int nj = 0; nj < 2; nj++)
#pragma unroll
                for (int mi = 0; mi < 4; mi++)
                    mma_bf16(acc1[mi][nj], av[mi], bv[nj][0], bv[nj][1]);
        }
#pragma unroll
        for (int mi = 0; mi < 4; mi++) {
            int r0 = wm*64 + mi*16 + gid;
#pragma unroll
            for (int nj = 0; nj < 2; nj++) {
                int colh = wn*16 + nj*8 + 2*tig;
                float2 bb = *(const float2*)&fc1b[t*64 + colh];
                __nv_bfloat162 p0 = __floats2bfloat162_rn(
                    gelu_exact(acc1[mi][nj][0] + bb.x),
                    gelu_exact(acc1[mi][nj][1] + bb.y));
                __nv_bfloat162 p1 = __floats2bfloat162_rn(
                    gelu_exact(acc1[mi][nj][2] + bb.x),
                    gelu_exact(acc1[mi][nj][3] + bb.y));
                *(__nv_bfloat162*)(smc + MSH + r0*144 + colh*2) = p0;
                *(__nv_bfloat162*)(smc + MSH + (r0+8)*144 + colh*2) = p1;
            }
        }
        __syncthreads();

        uint32_t bB2 = sbase + MSB2 + buf*27648
                     + (wn*48 + (l2 & 7))*144 + ((l2 >> 3) & 1)*16;
#pragma unroll
        for (int ks = 0; ks < 4; ks++) {
            uint32_t av[4][4], bv[6][2];
#pragma unroll
            for (int mi = 0; mi < 4; mi++)
                ldsm_x4(av[mi], aH + mi*16*144 + ks*32);
#pragma unroll
            for (int ni = 0; ni < 6; ni++)
                ldsm_x2(bv[ni], bB2 + ni*8*144 + ks*32);
#pragma unroll
            for (int ni = 0; ni < 6; ni++)
#pragma unroll
                for (int mi = 0; mi < 4; mi++)
                    mma_bf16(acc2[mi][ni], av[mi], bv[ni][0], bv[ni][1]);
        }
        __syncthreads();
        if (t + 2 < 12) {
            mlp_stage_b(smc, wfc1, wfc2, t + 2, tid);
            cp_commit();
        }
    }

#pragma unroll
    for (int mi = 0; mi < 4; mi++) {
        int r0 = row0 + wm*64 + mi*16 + gid;
#pragma unroll
        for (int ni = 0; ni < 6; ni++) {
            int col = wn*48 + ni*8 + 2*tig;
            float2 bb = *(const float2*)&fc2b[col];
            size_t o0 = (size_t)r0*192 + col;
            size_t o1 = (size_t)(r0 + 8)*192 + col;
            float2 r0v = *(const float2*)&res[o0];
            float2 r1v = *(const float2*)&res[o1];
            *(float2*)&out[o0] = make_float2(acc2[mi][ni][0] + bb.x + r0v.x,
                                             acc2[mi][ni][1] + bb.y + r0v.y);
            *(float2*)&out[o1] = make_float2(acc2[mi][ni][2] + bb.x + r1v.x,
                                             acc2[mi][ni][3] + bb.y + r1v.y);
        }
    }
}

// ---------------------------------------------------------------------------
// Attention core v3 (round-13 proven): mma.sync flash-style,
// one 128-thread block per (window, head).
// ---------------------------------------------------------------------------
#define QST 40
#define VST 72

__global__ __launch_bounds__(128) void attn_mma(
    const __nv_bfloat16* __restrict__ qkv, __nv_bfloat16* __restrict__ aout)
{
    __shared__ __nv_bfloat16 sQ[64*QST];
    __shared__ __nv_bfloat16 sK[64*QST];
    __shared__ __nv_bfloat16 sVT[32*VST];

    int widx = blockIdx.x;
    int head = blockIdx.y;
    int b  = widx >> 6;
    int wi = (widx >> 3) & 7;
    int wj = widx & 7;
    int tid  = threadIdx.x;
    int warp = tid >> 5, lane = tid & 31;
    int gid = lane >> 2, tig = lane & 3, l2 = lane & 15;
    const float scale = 0.17677669529663687f;
    const __nv_bfloat16 bz = __float2bfloat16(0.f);

    for (int i = tid; i < 15*QST; i += 128) {
        sQ[49*QST + i] = bz;
        sK[49*QST + i] = bz;
    }
    for (int i = tid; i < 32*15; i += 128) {
        int d = i / 15, c = 49 + i % 15;
        sVT[d*VST + c] = bz;
    }

    for (int idx = tid; idx < NTOK*4; idx += 128) {
        int n = idx >> 2, d8 = (idx & 3) << 3;
        int h  = (n/7)*8 + wi;
        int w2 = (n%7)*8 + wj;
        const __nv_bfloat16* bp =
            qkv + ((size_t)((b*HH + h)*WW) + w2)*576 + head*32 + d8;
        uint4 qv = *(const uint4*)bp;
        uint4 kv = *(const uint4*)(bp + 192);
        uint4 vv = *(const uint4*)(bp + 384);
        *(uint4*)&sQ[n*QST + d8] = qv;
        *(uint4*)&sK[n*QST + d8] = kv;
        __nv_bfloat16 vt[8];
        *(uint4*)vt = vv;
#pragma unroll
        for (int j = 0; j < 8; j++) sVT[(d8 + j)*VST + n] = vt[j];
    }
    __syncthreads();

    uint32_t qb = (uint32_t)__cvta_generic_to_shared(sQ);
    uint32_t kb = (uint32_t)__cvta_generic_to_shared(sK);
    uint32_t vb = (uint32_t)__cvta_generic_to_shared(sVT);

    int m0 = warp*16;
    uint32_t aQ = qb + (uint32_t)((m0 + (lane & 7) + ((lane >> 3) & 1)*8)*80
                                  + ((lane >> 4) & 1)*16);
    uint32_t bK = kb + (uint32_t)((l2 & 7)*80 + ((l2 >> 3) & 1)*16);
    uint32_t bV = vb + (uint32_t)((l2 & 7)*144 + ((l2 >> 3) & 1)*16);

    float sacc[8][4];
#pragma unroll
    for (int nt = 0; nt < 8; nt++)
#pragma unroll
        for (int j = 0; j < 4; j++) sacc[nt][j] = 0.f;
#pragma unroll
    for (int ks = 0; ks < 2; ks++) {
        uint32_t av[4];
        ldsm_x4(av, aQ + ks*32);
#pragma unroll
        for (int nt = 0; nt < 8; nt++) {
            uint32_t bv[2];
            ldsm_x2(bv, bK + nt*8*80 + ks*32);
            mma_bf16(sacc[nt], av, bv[0], bv[1]);
        }
    }

    const float NEG = -1e30f;
    float rmax0 = NEG, rmax1 = NEG;
#pragma unroll
    for (int nt = 0; nt < 8; nt++) {
        int c0 = nt*8 + 2*tig;
        bool v0 = c0 < NTOK, v1 = (c0 + 1) < NTOK;
        sacc[nt][0] = v0 ? sacc[nt][0]*scale : NEG;
        sacc[nt][1] = v1 ? sacc[nt][1]*scale : NEG;
        sacc[nt][2] = v0 ? sacc[nt][2]*scale : NEG;
        sacc[nt][3] = v1 ? sacc[nt][3]*scale : NEG;
        rmax0 = fmaxf(rmax0, fmaxf(sacc[nt][0], sacc[nt][1]));
        rmax1 = fmaxf(rmax1, fmaxf(sacc[nt][2], sacc[nt][3]));
    }
    rmax0 = fmaxf(rmax0, __shfl_xor_sync(0xffffffffu, rmax0, 1));
    rmax0 = fmaxf(rmax0, __shfl_xor_sync(0xffffffffu, rmax0, 2));
    rmax1 = fmaxf(rmax1, __shfl_xor_sync(0xffffffffu, rmax1, 1));
    rmax1 = fmaxf(rmax1, __shfl_xor_sync(0xffffffffu, rmax1, 2));
    float rsum0 = 0.f, rsum1 = 0.f;
#pragma unroll
    for (int nt = 0; nt < 8; nt++) {
        sacc[nt][0] = expf(sacc[nt][0] - rmax0);
        sacc[nt][1] = expf(sacc[nt][1] - rmax0);
        sacc[nt][2] = expf(sacc[nt][2] - rmax1);
        sacc[nt][3] = expf(sacc[nt][3] - rmax1);
        rsum0 += sacc[nt][0] + sacc[nt][1];
        rsum1 += sacc[nt][2] + sacc[nt][3];
    }
    rsum0 += __shfl_xor_sync(0xffffffffu, rsum0, 1);
    rsum0 += __shfl_xor_sync(0xffffffffu, rsum0, 2);
    rsum1 += __shfl_xor_sync(0xffffffffu, rsum1, 1);
    rsum1 += __shfl_xor_sync(0xffffffffu, rsum1, 2);
    float inv0 = 1.f / rsum0, inv1 = 1.f / rsum1;

    float oacc[4][4];
#pragma unroll
    for (int nd = 0; nd < 4; nd++)
#pragma unroll
        for (int j = 0; j < 4; j++) oacc[nd][j] = 0.f;
#pragma unroll
    for (int s = 0; s < 4; s++) {
        uint32_t av[4];
        __nv_bfloat162 t;
        t = __floats2bfloat162_rn(sacc[2*s][0]*inv0, sacc[2*s][1]*inv0);
        av[0] = *(uint32_t*)&t;
        t = __floats2bfloat162_rn(sacc[2*s][2]*inv1, sacc[2*s][3]*inv1);
        av[1] = *(uint32_t*)&t;
        t = __floats2bfloat162_rn(sacc[2*s+1][0]*inv0, sacc[2*s+1][1]*inv0);
        av[2] = *(uint32_t*)&t;
        t = __floats2bfloat162_rn(sacc[2*s+1][2]*inv1, sacc[2*s+1][3]*inv1);
        av[3] = *(uint32_t*)&t;
#pragma unroll
        for (int nd = 0; nd < 4; nd++) {
            uint32_t bv[2];
            ldsm_x2(bv, bV + nd*8*144 + s*32);
            mma_bf16(oacc[nd], av, bv[0], bv[1]);
        }
    }

#pragma unroll
    for (int r = 0; r < 2; r++) {
        int m = m0 + gid + r*8;
        if (m < NTOK) {
            int h  = (m/7)*8 + wi;
            int w2 = (m%7)*8 + wj;
            __nv_bfloat16* op =
                aout + ((size_t)((b*HH + h)*WW) + w2)*CC + head*HDIM;
#pragma unroll
            for (int nd = 0; nd < 4; nd++) {
                __nv_bfloat162 pv = __floats2bfloat162_rn(oacc[nd][2*r],
                                                          oacc[nd][2*r + 1]);
                *(__nv_bfloat162*)&op[nd*8 + 2*tig] = pv;
            }
        }
    }
}

// ---------------------------------------------------------------------------
extern "C" void kernel_launch(void* const* d_in, const int* in_sizes, int n_in,
                              void* d_out, int out_size)
{
    int p = 0;
    const float* x = (const float*)d_in[p++];
    while (p < n_in && in_sizes[p] == 1) p++;   // skip scalar H, W if present
    const float* cpe0_w = (const float*)d_in[p++];
    const float* cpe0_b = (const float*)d_in[p++];
    const float* cpe1_w = (const float*)d_in[p++];
    const float* cpe1_b = (const float*)d_in[p++];
    const float* n1_g   = (const float*)d_in[p++];
    const float* n1_b   = (const float*)d_in[p++];
    const float* qkv_w  = (const float*)d_in[p++];
    const float* qkv_b  = (const float*)d_in[p++];
    const float* proj_w = (const float*)d_in[p++];
    const float* proj_b = (const float*)d_in[p++];
    const float* n2_g   = (const float*)d_in[p++];
    const float* n2_b   = (const float*)d_in[p++];
    const float* fc1_w  = (const float*)d_in[p++];
    const float* fc1_b  = (const float*)d_in[p++];
    const float* fc2_w  = (const float*)d_in[p++];
    const float* fc2_b  = (const float*)d_in[p++];

    float *b0, *b1, *b2, *bqkv;
    __nv_bfloat16 *xn, *attn, *qkv, *wqkv, *wproj, *wfc1, *wfc2;
    cudaGetSymbolAddress((void**)&b0, g_buf0);
    cudaGetSymbolAddress((void**)&b1, g_buf1);
    cudaGetSymbolAddress((void**)&b2, g_buf2);
    cudaGetSymbolAddress((void**)&xn, g_xn);
    cudaGetSymbolAddress((void**)&attn, g_attn);
    cudaGetSymbolAddress((void**)&qkv, g_qkv);
    cudaGetSymbolAddress((void**)&wqkv, g_wqkv);
    cudaGetSymbolAddress((void**)&bqkv, g_bqkv);
    cudaGetSymbolAddress((void**)&wproj, g_wproj);
    cudaGetSymbolAddress((void**)&wfc1, g_wfc1);
    cudaGetSymbolAddress((void**)&wfc2, g_wfc2);

    cudaFuncSetAttribute(gemm_bf16<192,3>,
                         cudaFuncAttributeMaxDynamicSharedMemorySize, GEMM_SMEM_BYTES);
    cudaFuncSetAttribute(gemm_bf16<192,2>,
                         cudaFuncAttributeMaxDynamicSharedMemorySize, GEMM_SMEM_BYTES);
    cudaFuncSetAttribute(mlp_fused,
                         cudaFuncAttributeMaxDynamicSharedMemorySize, MLP_SMEM);

    dim3 gcpe(HH, BATCH);
    const int MB = TOKENS/128;   // 784

    prep_weights<<<dim3(576, 4), 256>>>(qkv_w, qkv_b, proj_w, fc1_w, fc2_w,
                                        wqkv, bqkv, wproj, wfc1, wfc2);
    cpe_kernel<<<gcpe, CC>>>(x, cpe0_w, cpe0_b, b0);
    ln_kernel<<<TOKENS/8, 256>>>(b0, n1_g, n1_b, xn);
    gemm_bf16<192,3><<<dim3(6, MB), 256, GEMM_SMEM_BYTES>>>(
        xn, wqkv, bqkv, nullptr, qkv, 576);
    attn_mma<<<dim3(BATCH*64, NHEAD), 128>>>(qkv, attn);
    gemm_bf16<192,2><<<dim3(2, MB), 256, GEMM_SMEM_BYTES>>>(
        attn, wproj, proj_b, b0, b1, 192);
    cpe_kernel<<<gcpe, CC>>>(b1, cpe1_w, cpe1_b, b2);
    ln_kernel<<<TOKENS/8, 256>>>(b2, n2_g, n2_b, xn);
    mlp_fused<<<MB, 256, MLP_SMEM>>>(xn, wfc1, fc1_b, wfc2, fc2_b,
                                     b2, (float*)d_out);
}